// round 11
// baseline (speedup 1.0000x reference)
#include <cuda_runtime.h>
#include <math.h>

#define NB    8
#define NC    64
#define NPIX  1600
#define TOPK  10
#define TKPAD 12
#define NNZ   (NPIX * TOPK)
#define SORTN 2048
#define FULLW 0xFFFFFFFFu
#define NBLK  112
#define NTHR  1024

// ---------------- static scratch (no runtime allocation) ----------------
__device__ float g_xx  [NB * NPIX];
__device__ int   g_topk[NB * NPIX * TKPAD];
__device__ float g_dv2 [NB * NPIX];
__device__ int   g_off [NB * (NPIX + 1)];
__device__ int   g_ecol[NB * NNZ];
__device__ float g_Z   [NB * NPIX * NC];
__device__ float g_Y   [NB * NPIX * NC];
__device__ float g_Hf  [NB * NPIX * NC];

// software grid barrier state (cnt self-resets; gen monotonic across replays)
__device__ int          g_cnt = 0;
__device__ volatile int g_gen = 0;

__device__ __forceinline__ float4 f4add(float4 a, float4 b) {
    a.x += b.x; a.y += b.y; a.z += b.z; a.w += b.w; return a;
}
__device__ __forceinline__ unsigned long long u64min_(unsigned long long a, unsigned long long b) { return a < b ? a : b; }
__device__ __forceinline__ unsigned long long u64max_(unsigned long long a, unsigned long long b) { return a > b ? a : b; }

union SmemU {
    struct {
        unsigned long long skey[SORTN];       // 16384 B
        unsigned short rs[NPIX], re[NPIX], pos[NPIX];
        int dv[NPIX];
        int off[NPIX + 1];
        int part[NTHR];
    } b;                                      // ~42.9 KB
    struct { float As[4096]; float Ws[4096]; } g;   // 32 KB
    struct { float4 red[NTHR]; } v;           // 16 KB
};

__device__ __forceinline__ void gbar() {
    __syncthreads();
    if (threadIdx.x == 0) {
        __threadfence();
        int mygen = g_gen;
        if (atomicAdd(&g_cnt, 1) == NBLK - 1) {
            g_cnt = 0;
            __threadfence();
            g_gen = mygen + 1;
        } else {
            while (g_gen == mygen) { __nanosleep(64); }
            __threadfence();
        }
    }
    __syncthreads();
}

// ---- build phase body (port of k_build, per-batch block) ----
__device__ void build_phase(SmemU* sm, int b) {
    int t = threadIdx.x;
    int lane = t & 31, wid = t >> 5;
    unsigned long long* skey = sm->b.skey;
    unsigned short* rs = sm->b.rs; unsigned short* re = sm->b.re; unsigned short* pos = sm->b.pos;
    int* dv = sm->b.dv; int* off = sm->b.off; int* part = sm->b.part;

    // softmax over relu logits
    float* rf = (float*)part;
    float v0 = g_xx[b*NPIX + t];
    float v1 = (t + 1024 < NPIX) ? g_xx[b*NPIX + t + 1024] : -3.4e38f;
    rf[t] = fmaxf(v0, v1); __syncthreads();
    for (int s = 512; s > 0; s >>= 1) { if (t < s) rf[t] = fmaxf(rf[t], rf[t+s]); __syncthreads(); }
    float mx = rf[0]; __syncthreads();
    float e0 = expf(v0 - mx);
    float e1 = (t + 1024 < NPIX) ? expf(v1 - mx) : 0.f;
    rf[t] = e0 + e1; __syncthreads();
    for (int s = 512; s > 0; s >>= 1) { if (t < s) rf[t] += rf[t+s]; __syncthreads(); }
    float inv = 1.f / rf[0]; __syncthreads();

    unsigned long long a0 = ((unsigned long long)__float_as_uint(e0 * inv) << 32) | (unsigned)t;
    unsigned long long a1 = (t + 1024 < NPIX)
        ? (((unsigned long long)__float_as_uint(e1 * inv) << 32) | (unsigned)(t + 1024))
        : 0xFFFFFFFFFFFFFFFFull;

    #define REGPHASE(KSZ, J) { \
        unsigned long long p0 = __shfl_xor_sync(FULLW, a0, (J)); \
        unsigned long long p1 = __shfl_xor_sync(FULLW, a1, (J)); \
        int i0 = t, i1 = t + 1024; \
        bool m0 = (((i0 & (J)) == 0) == ((i0 & (KSZ)) == 0)); \
        bool m1 = (((i1 & (J)) == 0) == ((i1 & (KSZ)) == 0)); \
        a0 = m0 ? u64min_(a0, p0) : u64max_(a0, p0); \
        a1 = m1 ? u64min_(a1, p1) : u64max_(a1, p1); }

    for (int ksz = 2; ksz <= 32; ksz <<= 1)
        for (int j = ksz >> 1; j >= 1; j >>= 1)
            REGPHASE(ksz, j);
    skey[t] = a0; skey[t + 1024] = a1; __syncthreads();

    for (int ksz = 64; ksz <= SORTN; ksz <<= 1) {
        int jstart = ksz >> 1;
        if (ksz == SORTN) {
            unsigned long long lo = u64min_(a0, a1), hi = u64max_(a0, a1);
            a0 = lo; a1 = hi;
            skey[t] = a0; skey[t + 1024] = a1; __syncthreads();
            jstart = 512;
        }
        for (int j = jstart; j >= 32; j >>= 1) {
            #pragma unroll
            for (int r = 0; r < 2; r++) {
                int i = t + r * 1024;
                int ixj = i ^ j;
                if (ixj > i) {
                    unsigned long long a = skey[i], c = skey[ixj];
                    bool up = ((i & ksz) == 0);
                    if ((a > c) == up) { skey[i] = c; skey[ixj] = a; }
                }
            }
            __syncthreads();
        }
        a0 = skey[t]; a1 = skey[t + 1024];
        for (int j = 16; j >= 1; j >>= 1)
            REGPHASE(ksz, j);
        skey[t] = a0; skey[t + 1024] = a1; __syncthreads();
    }

    // run bounds; pos scatter; DV=0
    for (int p = t; p < NPIX; p += 1024) {
        unsigned v = (unsigned)(skey[p] >> 32);
        int lo = 0, hi = p;
        while (lo < hi) { int m = (lo + hi) >> 1;
            if ((unsigned)(skey[m] >> 32) < v) lo = m + 1; else hi = m; }
        rs[p] = (unsigned short)lo;
        int lo2 = p + 1, hi2 = NPIX;
        while (lo2 < hi2) { int m = (lo2 + hi2) >> 1;
            if ((unsigned)(skey[m] >> 32) <= v) lo2 = m + 1; else hi2 = m; }
        re[p] = (unsigned short)(lo2 - 1);
        pos[(unsigned)(skey[p] & 0xFFFFFFFFu)] = (unsigned short)p;
        dv[p] = 0;
    }
    __syncthreads();

    // per-row top-k walk (exact stable-argsort (d,idx) semantics incl. ties)
    for (int i = t; i < NPIX; i += 1024) {
        int p = pos[i];
        float vi = __uint_as_float((unsigned)(skey[p] >> 32));
        int out[TOPK]; int cnt = 0;
        int a = rs[p], bnd = re[p];
        for (int q = a; q <= bnd && cnt < TOPK; q++)
            out[cnt++] = (int)(skey[q] & 0xFFFFFFFFu);
        int L = a - 1, R = bnd + 1;
        while (cnt < TOPK) {
            float dL = (L >= 0)   ? vi - __uint_as_float((unsigned)(skey[L] >> 32)) : 3.4e38f;
            float dR = (R < NPIX) ? __uint_as_float((unsigned)(skey[R] >> 32)) - vi : 3.4e38f;
            if (dL < dR) {
                int s2 = rs[L];
                for (int q = s2; q <= L && cnt < TOPK; q++)
                    out[cnt++] = (int)(skey[q] & 0xFFFFFFFFu);
                L = s2 - 1;
            } else if (dR < dL) {
                int e2 = re[R];
                for (int q = R; q <= e2 && cnt < TOPK; q++)
                    out[cnt++] = (int)(skey[q] & 0xFFFFFFFFu);
                R = e2 + 1;
            } else {
                int sL = rs[L], eR = re[R];
                int qa = sL, qb = R;
                while (cnt < TOPK && (qa <= L || qb <= eR)) {
                    int ia = (qa <= L)  ? (int)(skey[qa] & 0xFFFFFFFFu) : 0x7FFFFFFF;
                    int ib = (qb <= eR) ? (int)(skey[qb] & 0xFFFFFFFFu) : 0x7FFFFFFF;
                    if (ia < ib) { out[cnt++] = ia; qa++; }
                    else         { out[cnt++] = ib; qb++; }
                }
                L = sL - 1; R = eR + 1;
            }
        }
        bool has = false;
        #pragma unroll
        for (int j2 = 0; j2 < TOPK; j2++) has |= (out[j2] == i);
        if (!has) out[TOPK-1] = i;

        int base = (b*NPIX + i) * TKPAD;
        #pragma unroll
        for (int j2 = 0; j2 < TOPK; j2++) {
            g_topk[base + j2] = out[j2];
            atomicAdd(&dv[out[j2]], 1);
        }
    }
    __syncthreads();

    // exclusive scan (pairs) via shfl, 3 barriers
    int p0 = t * 2;
    int sv = (p0 < NPIX) ? dv[p0] + dv[p0+1] : 0;
    int incl = sv;
    #pragma unroll
    for (int d2 = 1; d2 < 32; d2 <<= 1) {
        int vv = __shfl_up_sync(FULLW, incl, d2);
        if (lane >= d2) incl += vv;
    }
    if (lane == 31) part[wid] = incl;
    __syncthreads();
    if (wid == 0) {
        int w = part[lane];
        #pragma unroll
        for (int d2 = 1; d2 < 32; d2 <<= 1) {
            int vv = __shfl_up_sync(FULLW, w, d2);
            if (lane >= d2) w += vv;
        }
        part[lane] = w;
    }
    __syncthreads();
    int total_incl = incl + (wid ? part[wid-1] : 0);
    if (p0 < NPIX) {
        int excl = total_incl - sv;
        off[p0] = excl; off[p0+1] = excl + dv[p0];
        g_off[b*(NPIX+1) + p0]     = excl;
        g_off[b*(NPIX+1) + p0 + 1] = excl + dv[p0];
        g_dv2[b*NPIX + p0]     = rsqrtf((float)dv[p0]);
        g_dv2[b*NPIX + p0 + 1] = rsqrtf((float)dv[p0+1]);
    }
    if (t == 0) { off[NPIX] = NNZ; g_off[b*(NPIX+1) + NPIX] = NNZ; }
    __syncthreads();

    // CSR fill
    for (int p = t; p < NPIX; p += 1024) dv[p] = 0;
    __syncthreads();
    for (int s2 = t; s2 < NNZ; s2 += 1024) {
        int e = s2 / TOPK, j2 = s2 - e * TOPK;
        int v = g_topk[(b*NPIX + e) * TKPAD + j2];
        int ppos = atomicAdd(&dv[v], 1);
        g_ecol[b*NNZ + off[v] + ppos] = e;
    }
}

// ---- gemm phase: block-stride over 200 tiles, 256 active compute threads ----
__device__ void gemm_phase(SmemU* sm, const float* __restrict__ X,
                           const float* __restrict__ W,
                           const float* __restrict__ bias, int useH) {
    int t = threadIdx.x;
    float* As = sm->g.As; float* Ws = sm->g.Ws;
    for (int tile = blockIdx.x; tile < 200; tile += NBLK) {
        int b  = tile / 25;
        int r0 = (tile - b * 25) * 64;
        const float* Xb = (useH ? g_Hf : X) + ((size_t)b * NPIX + r0) * NC;
        for (int i = t; i < 4096; i += 1024) { As[i] = Xb[i]; Ws[i] = W[i]; }
        __syncthreads();
        if (t < 256) {
            int tx = t & 15, ty = t >> 4;
            int c4 = tx * 4, r4 = ty * 4;
            float acc[4][4];
            #pragma unroll
            for (int i = 0; i < 4; i++)
                #pragma unroll
                for (int j = 0; j < 4; j++) acc[i][j] = 0.f;
            for (int k = 0; k < 64; k += 4) {
                float4 w0 = *(const float4*)&Ws[(k+0)*64 + c4];
                float4 w1 = *(const float4*)&Ws[(k+1)*64 + c4];
                float4 w2 = *(const float4*)&Ws[(k+2)*64 + c4];
                float4 w3 = *(const float4*)&Ws[(k+3)*64 + c4];
                #pragma unroll
                for (int i = 0; i < 4; i++) {
                    float4 a = *(const float4*)&As[(r4+i)*64 + k];
                    acc[i][0] += a.x*w0.x + a.y*w1.x + a.z*w2.x + a.w*w3.x;
                    acc[i][1] += a.x*w0.y + a.y*w1.y + a.z*w2.y + a.w*w3.y;
                    acc[i][2] += a.x*w0.z + a.y*w1.z + a.z*w2.z + a.w*w3.z;
                    acc[i][3] += a.x*w0.w + a.y*w1.w + a.z*w2.w + a.w*w3.w;
                }
            }
            float4 bv = *(const float4*)&bias[c4];
            #pragma unroll
            for (int i = 0; i < 4; i++) {
                int r = r0 + r4 + i;
                float s = 0.1f * g_dv2[b*NPIX + r];
                float4 o;
                o.x = (acc[i][0] + bv.x) * s;
                o.y = (acc[i][1] + bv.y) * s;
                o.z = (acc[i][2] + bv.z) * s;
                o.w = (acc[i][3] + bv.w) * s;
                *(float4*)&g_Z[((size_t)b*NPIX + r) * NC + c4] = o;
            }
        }
        __syncthreads();
    }
}

// ---- edge phase: thread-task stride over NB*NPIX*16 ----
__device__ void edge_phase() {
    for (int task = blockIdx.x * NTHR + threadIdx.x; task < NB*NPIX*16; task += NBLK*NTHR) {
        int eg = task >> 4;
        int c4 = (task & 15) * 4;
        int b = eg / NPIX;
        int e = eg - b * NPIX;
        const int* __restrict__ tk = &g_topk[(b*NPIX + e) * TKPAD];
        int4 i0 = *(const int4*)tk;
        int4 i1 = *(const int4*)(tk + 4);
        int2 i2 = *(const int2*)(tk + 8);
        float4 acc;
        acc =            *(const float4*)&g_Z[((b*NPIX + i0.x) << 6) + c4];
        acc = f4add(acc, *(const float4*)&g_Z[((b*NPIX + i0.y) << 6) + c4]);
        acc = f4add(acc, *(const float4*)&g_Z[((b*NPIX + i0.z) << 6) + c4]);
        acc = f4add(acc, *(const float4*)&g_Z[((b*NPIX + i0.w) << 6) + c4]);
        acc = f4add(acc, *(const float4*)&g_Z[((b*NPIX + i1.x) << 6) + c4]);
        acc = f4add(acc, *(const float4*)&g_Z[((b*NPIX + i1.y) << 6) + c4]);
        acc = f4add(acc, *(const float4*)&g_Z[((b*NPIX + i1.z) << 6) + c4]);
        acc = f4add(acc, *(const float4*)&g_Z[((b*NPIX + i1.w) << 6) + c4]);
        acc = f4add(acc, *(const float4*)&g_Z[((b*NPIX + i2.x) << 6) + c4]);
        acc = f4add(acc, *(const float4*)&g_Z[((b*NPIX + i2.y) << 6) + c4]);
        *(float4*)&g_Y[((b*NPIX + e) << 6) + c4] = acc;
    }
}

// ---- vertex phase: 4 sub-blocks of 256 threads, block-stride over 3200 groups ----
__device__ void vertex_phase(SmemU* sm) {
    int t = threadIdx.x;
    int s  = t >> 8;          // sub-block 0..3
    int st = t & 255;
    int c4 = (st & 15) * 4, sl = st >> 4;   // slice 0..15
    float4* red = sm->v.red;
    for (int vg = blockIdx.x; vg < (NB*NPIX)/4; vg += NBLK) {
        int vid = vg * 4 + s;
        int b = vid / NPIX;
        int u = vid - b * NPIX;
        int o0 = g_off[b*(NPIX+1) + u];
        int o1 = g_off[b*(NPIX+1) + u + 1];
        float4 acc = make_float4(0.f, 0.f, 0.f, 0.f);
        for (int p = o0 + sl; p < o1; p += 16) {
            int e = g_ecol[b*NNZ + p];
            acc = f4add(acc, *(const float4*)&g_Y[((b*NPIX + e) << 6) + c4]);
        }
        red[t] = acc; __syncthreads();
        if (st < 128) red[t] = f4add(red[t], red[t+128]); __syncthreads();
        if (st < 64)  red[t] = f4add(red[t], red[t+64]);  __syncthreads();
        if (st < 32)  red[t] = f4add(red[t], red[t+32]);  __syncthreads();
        if (st < 16) {
            float4 tot = f4add(red[t], red[t+16]);
            float sc = g_dv2[b*NPIX + u];
            float4 o;
            o.x = fmaxf(tot.x * sc, 0.f);
            o.y = fmaxf(tot.y * sc, 0.f);
            o.z = fmaxf(tot.z * sc, 0.f);
            o.w = fmaxf(tot.w * sc, 0.f);
            *(float4*)&g_Hf[((b*NPIX + u) << 6) + st*4] = o;
        }
        __syncthreads();
    }
}

// ---- the single fused kernel ----
__global__ __launch_bounds__(NTHR, 1) void k_all(
    const float* __restrict__ x,
    const float* __restrict__ w_con1, const float* __restrict__ b_con1,
    const float* __restrict__ W1, const float* __restrict__ b1,
    const float* __restrict__ W2, const float* __restrict__ b2,
    const float* __restrict__ w_con2, const float* __restrict__ b_con2,
    float* __restrict__ out)
{
    __shared__ SmemU sm;
    int gt = blockIdx.x * NTHR + threadIdx.x;

    // P0: conv + relu (logits), zero out[]
    if (gt < NB) out[gt] = 0.f;
    if (gt < NB * NPIX) {
        int b = gt / NPIX, p = gt - b * NPIX;
        const float* xb = x + (size_t)b * NC * NPIX;
        float acc = b_con1[0];
        #pragma unroll
        for (int c = 0; c < NC; c++) acc += xb[c*NPIX + p] * w_con1[c];
        g_xx[b*NPIX + p] = fmaxf(acc, 0.f);
    }
    gbar();

    // P1: graph build (blocks 0..7)
    if (blockIdx.x < NB) build_phase(&sm, blockIdx.x);
    gbar();

    // layer 1
    gemm_phase(&sm, x, W1, b1, 0);
    gbar();
    edge_phase();
    gbar();
    vertex_phase(&sm);
    gbar();

    // layer 2
    gemm_phase(&sm, nullptr, W2, b2, 1);
    gbar();
    edge_phase();
    gbar();
    vertex_phase(&sm);
    gbar();

    // P8: final conv + relu + per-batch sum
    if (gt < NB * NPIX) {
        int b = gt / NPIX, p = gt - b * NPIX;
        const float* hb = g_Hf + (size_t)b * NPIX * NC;   // raw reshape: (C, NPIX)
        float acc = b_con2[0];
        #pragma unroll
        for (int c = 0; c < NC; c++) acc += hb[c*NPIX + p] * w_con2[c];
        atomicAdd(&out[b], fmaxf(acc, 0.f));
    }
}

// ---------------- launch ----------------
extern "C" void kernel_launch(void* const* d_in, const int* in_sizes, int n_in,
                              void* d_out, int out_size)
{
    const float* x      = (const float*)d_in[0];
    const float* w_con1 = (const float*)d_in[1];
    const float* b_con1 = (const float*)d_in[2];
    const float* W1     = (const float*)d_in[3];
    const float* b1     = (const float*)d_in[4];
    const float* W2     = (const float*)d_in[5];
    const float* b2     = (const float*)d_in[6];
    const float* w_con2 = (const float*)d_in[7];
    const float* b_con2 = (const float*)d_in[8];
    float* out = (float*)d_out;

    k_all<<<NBLK, NTHR>>>(x, w_con1, b_con1, W1, b1, W2, b2, w_con2, b_con2, out);
}

// round 12
// speedup vs baseline: 1.6724x; 1.6724x over previous
#include <cuda_runtime.h>
#include <math.h>

#define NB    8
#define NC    64
#define NPIX  1600
#define TOPK  10
#define TKPAD 12
#define NNZ   (NPIX * TOPK)
#define SORTN 2048
#define FULLW 0xFFFFFFFFu

// ---------------- static scratch (no runtime allocation) ----------------
__device__ float g_xx  [NB * NPIX];
__device__ unsigned long long g_skey[NB * NPIX];   // sorted (val,idx) keys
__device__ unsigned short g_rs[NB * NPIX];         // run start per sorted pos
__device__ unsigned short g_re[NB * NPIX];         // run end per sorted pos
__device__ int   g_dvc [NB * NPIX];                // DV counters (global)
__device__ int   g_cur [NB * NPIX];                // CSR fill cursors
__device__ int   g_topk[NB * NPIX * TKPAD];
__device__ float g_dv2 [NB * NPIX];
__device__ int   g_off [NB * (NPIX + 1)];
__device__ int   g_ecol[NB * NNZ];
__device__ float g_Z   [NB * NPIX * NC];
__device__ float g_Y   [NB * NPIX * NC];
__device__ float g_Hf  [NB * NPIX * NC];

__device__ __forceinline__ float4 f4add(float4 a, float4 b) {
    a.x += b.x; a.y += b.y; a.z += b.z; a.w += b.w; return a;
}
__device__ __forceinline__ unsigned long long u64min_(unsigned long long a, unsigned long long b) { return a < b ? a : b; }
__device__ __forceinline__ unsigned long long u64max_(unsigned long long a, unsigned long long b) { return a > b ? a : b; }

// ---------------- K1: 1x1 conv + relu (logits); zero counters & out
__global__ void k_convA(const float* __restrict__ x,
                        const float* __restrict__ w,
                        const float* __restrict__ bconst,
                        float* __restrict__ out)
{
    int b = blockIdx.y, t = threadIdx.x;
    __shared__ float ws[NC];
    if (t < NC) ws[t] = w[t];
    __syncthreads();
    int gid = (blockIdx.y * 7 + blockIdx.x) * 256 + t;
    if (gid < NB * NPIX) { g_dvc[gid] = 0; g_cur[gid] = 0; }
    if (gid < NB) out[gid] = 0.f;
    int p = blockIdx.x * 256 + t;
    if (p >= NPIX) return;
    const float* xb = x + (size_t)b * NC * NPIX;
    float acc = bconst[0];
    #pragma unroll
    for (int c = 0; c < NC; c++) acc += xb[c*NPIX + p] * ws[c];
    g_xx[b*NPIX + p] = fmaxf(acc, 0.f);
}

// ---------------- K2: softmax + sort + run bounds (8 blocks)
__global__ __launch_bounds__(1024) void k_sortA()
{
    int b = blockIdx.x, t = threadIdx.x;
    __shared__ unsigned long long skey[SORTN];      // 16 KB
    __shared__ float rf[1024];

    // softmax over relu logits
    float v0 = g_xx[b*NPIX + t];
    float v1 = (t + 1024 < NPIX) ? g_xx[b*NPIX + t + 1024] : -3.4e38f;
    rf[t] = fmaxf(v0, v1); __syncthreads();
    for (int s = 512; s > 0; s >>= 1) { if (t < s) rf[t] = fmaxf(rf[t], rf[t+s]); __syncthreads(); }
    float mx = rf[0]; __syncthreads();
    float e0 = expf(v0 - mx);
    float e1 = (t + 1024 < NPIX) ? expf(v1 - mx) : 0.f;
    rf[t] = e0 + e1; __syncthreads();
    for (int s = 512; s > 0; s >>= 1) { if (t < s) rf[t] += rf[t+s]; __syncthreads(); }
    float inv = 1.f / rf[0]; __syncthreads();

    unsigned long long a0 = ((unsigned long long)__float_as_uint(e0 * inv) << 32) | (unsigned)t;
    unsigned long long a1 = (t + 1024 < NPIX)
        ? (((unsigned long long)__float_as_uint(e1 * inv) << 32) | (unsigned)(t + 1024))
        : 0xFFFFFFFFFFFFFFFFull;

    #define REGPHASE(KSZ, J) { \
        unsigned long long p0 = __shfl_xor_sync(FULLW, a0, (J)); \
        unsigned long long p1 = __shfl_xor_sync(FULLW, a1, (J)); \
        int i0 = t, i1 = t + 1024; \
        bool m0 = (((i0 & (J)) == 0) == ((i0 & (KSZ)) == 0)); \
        bool m1 = (((i1 & (J)) == 0) == ((i1 & (KSZ)) == 0)); \
        a0 = m0 ? u64min_(a0, p0) : u64max_(a0, p0); \
        a1 = m1 ? u64min_(a1, p1) : u64max_(a1, p1); }

    for (int ksz = 2; ksz <= 32; ksz <<= 1)
        for (int j = ksz >> 1; j >= 1; j >>= 1)
            REGPHASE(ksz, j);
    skey[t] = a0; skey[t + 1024] = a1; __syncthreads();

    for (int ksz = 64; ksz <= SORTN; ksz <<= 1) {
        int jstart = ksz >> 1;
        if (ksz == SORTN) {
            unsigned long long lo = u64min_(a0, a1), hi = u64max_(a0, a1);
            a0 = lo; a1 = hi;
            skey[t] = a0; skey[t + 1024] = a1; __syncthreads();
            jstart = 512;
        }
        for (int j = jstart; j >= 32; j >>= 1) {
            #pragma unroll
            for (int r = 0; r < 2; r++) {
                int i = t + r * 1024;
                int ixj = i ^ j;
                if (ixj > i) {
                    unsigned long long a = skey[i], c = skey[ixj];
                    bool up = ((i & ksz) == 0);
                    if ((a > c) == up) { skey[i] = c; skey[ixj] = a; }
                }
            }
            __syncthreads();
        }
        a0 = skey[t]; a1 = skey[t + 1024];
        for (int j = 16; j >= 1; j >>= 1)
            REGPHASE(ksz, j);
        skey[t] = a0; skey[t + 1024] = a1; __syncthreads();
    }

    // run bounds via binary search; spill sorted keys + bounds to global
    for (int p = t; p < NPIX; p += 1024) {
        unsigned v = (unsigned)(skey[p] >> 32);
        int lo = 0, hi = p;
        while (lo < hi) { int m = (lo + hi) >> 1;
            if ((unsigned)(skey[m] >> 32) < v) lo = m + 1; else hi = m; }
        int lo2 = p + 1, hi2 = NPIX;
        while (lo2 < hi2) { int m = (lo2 + hi2) >> 1;
            if ((unsigned)(skey[m] >> 32) <= v) lo2 = m + 1; else hi2 = m; }
        g_skey[b*NPIX + p] = skey[p];
        g_rs[b*NPIX + p] = (unsigned short)lo;
        g_re[b*NPIX + p] = (unsigned short)(lo2 - 1);
    }
}

// ---------------- K3: top-k walk, 8 slices per batch (64 blocks)
__global__ __launch_bounds__(256) void k_walk()
{
    int b = blockIdx.y, slice = blockIdx.x, t = threadIdx.x;
    __shared__ unsigned long long sk[NPIX];         // 12.8 KB
    __shared__ unsigned short rs[NPIX], re[NPIX];   // 6.4 KB
    for (int p = t; p < NPIX; p += 256) {
        sk[p] = g_skey[b*NPIX + p];
        rs[p] = g_rs[b*NPIX + p];
        re[p] = g_re[b*NPIX + p];
    }
    __syncthreads();
    if (t >= 200) return;
    int p = slice * 200 + t;                         // process by sorted position
    int i = (int)(sk[p] & 0xFFFFFFFFu);              // original row index
    float vi = __uint_as_float((unsigned)(sk[p] >> 32));

    int out[TOPK]; int cnt = 0;
    int a = rs[p], bnd = re[p];
    for (int q = a; q <= bnd && cnt < TOPK; q++)
        out[cnt++] = (int)(sk[q] & 0xFFFFFFFFu);
    int L = a - 1, R = bnd + 1;
    while (cnt < TOPK) {
        float dL = (L >= 0)   ? vi - __uint_as_float((unsigned)(sk[L] >> 32)) : 3.4e38f;
        float dR = (R < NPIX) ? __uint_as_float((unsigned)(sk[R] >> 32)) - vi : 3.4e38f;
        if (dL < dR) {
            int s2 = rs[L];
            for (int q = s2; q <= L && cnt < TOPK; q++)
                out[cnt++] = (int)(sk[q] & 0xFFFFFFFFu);
            L = s2 - 1;
        } else if (dR < dL) {
            int e2 = re[R];
            for (int q = R; q <= e2 && cnt < TOPK; q++)
                out[cnt++] = (int)(sk[q] & 0xFFFFFFFFu);
            R = e2 + 1;
        } else {                                      // exact distance tie: merge by idx
            int sL = rs[L], eR = re[R];
            int qa = sL, qb = R;
            while (cnt < TOPK && (qa <= L || qb <= eR)) {
                int ia = (qa <= L)  ? (int)(sk[qa] & 0xFFFFFFFFu) : 0x7FFFFFFF;
                int ib = (qb <= eR) ? (int)(sk[qb] & 0xFFFFFFFFu) : 0x7FFFFFFF;
                if (ia < ib) { out[cnt++] = ia; qa++; }
                else         { out[cnt++] = ib; qb++; }
            }
            L = sL - 1; R = eR + 1;
        }
    }
    bool has = false;
    #pragma unroll
    for (int j2 = 0; j2 < TOPK; j2++) has |= (out[j2] == i);
    if (!has) out[TOPK-1] = i;                        // reference self rule

    int base = (b*NPIX + i) * TKPAD;
    #pragma unroll
    for (int j2 = 0; j2 < TOPK; j2++) {
        g_topk[base + j2] = out[j2];
        atomicAdd(&g_dvc[b*NPIX + out[j2]], 1);
    }
}

// ---------------- K4: scan DV -> offsets; dv2 (8 blocks, shfl scan)
__global__ __launch_bounds__(1024) void k_scan()
{
    int b = blockIdx.x, t = threadIdx.x;
    int lane = t & 31, wid = t >> 5;
    __shared__ int part[32];
    int p0 = t * 2;
    int d0 = (p0 < NPIX) ? g_dvc[b*NPIX + p0] : 0;
    int d1 = (p0 + 1 < NPIX) ? g_dvc[b*NPIX + p0 + 1] : 0;
    int sv = d0 + d1;
    int incl = sv;
    #pragma unroll
    for (int d2 = 1; d2 < 32; d2 <<= 1) {
        int vv = __shfl_up_sync(FULLW, incl, d2);
        if (lane >= d2) incl += vv;
    }
    if (lane == 31) part[wid] = incl;
    __syncthreads();
    if (wid == 0) {
        int w = part[lane];
        #pragma unroll
        for (int d2 = 1; d2 < 32; d2 <<= 1) {
            int vv = __shfl_up_sync(FULLW, w, d2);
            if (lane >= d2) w += vv;
        }
        part[lane] = w;
    }
    __syncthreads();
    int total_incl = incl + (wid ? part[wid-1] : 0);
    if (p0 < NPIX) {
        int excl = total_incl - sv;
        g_off[b*(NPIX+1) + p0]     = excl;
        g_off[b*(NPIX+1) + p0 + 1] = excl + d0;
        g_dv2[b*NPIX + p0]     = rsqrtf((float)d0);
        g_dv2[b*NPIX + p0 + 1] = rsqrtf((float)d1);
    }
    if (t == 0) g_off[b*(NPIX+1) + NPIX] = NNZ;
}

// ---------------- K5: CSR fill, wide (global atomic cursors)
__global__ void k_fill()
{
    int b = blockIdx.y;
    int idx = blockIdx.x * 256 + threadIdx.x;
    if (idx >= NNZ) return;
    int e = idx / TOPK, j = idx - e * TOPK;
    int v = g_topk[(b*NPIX + e) * TKPAD + j];
    int ppos = atomicAdd(&g_cur[b*NPIX + v], 1);
    g_ecol[b*NNZ + g_off[b*(NPIX+1) + v] + ppos] = e;
}

// ---------------- K6/K9: Z[v,:] = 0.1*dv2[v] * (X[v,:] @ W + bias)
__global__ void k_gemm(const float* __restrict__ X,
                       const float* __restrict__ W,
                       const float* __restrict__ bias,
                       int useH)
{
    int b  = blockIdx.y;
    int r0 = blockIdx.x * 64;
    __shared__ float As[64 * 64];
    __shared__ float Ws[64 * 64];
    int t = threadIdx.x;
    const float* Xb = (useH ? g_Hf : X) + ((size_t)b * NPIX + r0) * NC;
    for (int i = t; i < 4096; i += 256) { As[i] = Xb[i]; Ws[i] = W[i]; }
    __syncthreads();

    int tx = t & 15, ty = t >> 4;
    int c4 = tx * 4, r4 = ty * 4;
    float acc[4][4];
    #pragma unroll
    for (int i = 0; i < 4; i++)
        #pragma unroll
        for (int j = 0; j < 4; j++) acc[i][j] = 0.f;

    for (int k = 0; k < 64; k += 4) {
        float4 w0 = *(const float4*)&Ws[(k+0)*64 + c4];
        float4 w1 = *(const float4*)&Ws[(k+1)*64 + c4];
        float4 w2 = *(const float4*)&Ws[(k+2)*64 + c4];
        float4 w3 = *(const float4*)&Ws[(k+3)*64 + c4];
        #pragma unroll
        for (int i = 0; i < 4; i++) {
            float4 a = *(const float4*)&As[(r4+i)*64 + k];
            acc[i][0] += a.x*w0.x + a.y*w1.x + a.z*w2.x + a.w*w3.x;
            acc[i][1] += a.x*w0.y + a.y*w1.y + a.z*w2.y + a.w*w3.y;
            acc[i][2] += a.x*w0.z + a.y*w1.z + a.z*w2.z + a.w*w3.z;
            acc[i][3] += a.x*w0.w + a.y*w1.w + a.z*w2.w + a.w*w3.w;
        }
    }
    float4 bv = *(const float4*)&bias[c4];
    #pragma unroll
    for (int i = 0; i < 4; i++) {
        int r = r0 + r4 + i;
        float s = 0.1f * g_dv2[b*NPIX + r];
        float4 o;
        o.x = (acc[i][0] + bv.x) * s;
        o.y = (acc[i][1] + bv.y) * s;
        o.z = (acc[i][2] + bv.z) * s;
        o.w = (acc[i][3] + bv.w) * s;
        *(float4*)&g_Z[((size_t)b*NPIX + r) * NC + c4] = o;
    }
}

// ---------------- K7/K10: hyperedge gather
__global__ void k_edge()
{
    int b = blockIdx.y, t = threadIdx.x;
    int e  = blockIdx.x * 16 + (t >> 4);
    int c4 = (t & 15) * 4;
    const int* __restrict__ tk = &g_topk[(b*NPIX + e) * TKPAD];
    int4 i0 = *(const int4*)tk;
    int4 i1 = *(const int4*)(tk + 4);
    int2 i2 = *(const int2*)(tk + 8);
    float4 acc;
    acc =            *(const float4*)&g_Z[((b*NPIX + i0.x) << 6) + c4];
    acc = f4add(acc, *(const float4*)&g_Z[((b*NPIX + i0.y) << 6) + c4]);
    acc = f4add(acc, *(const float4*)&g_Z[((b*NPIX + i0.z) << 6) + c4]);
    acc = f4add(acc, *(const float4*)&g_Z[((b*NPIX + i0.w) << 6) + c4]);
    acc = f4add(acc, *(const float4*)&g_Z[((b*NPIX + i1.x) << 6) + c4]);
    acc = f4add(acc, *(const float4*)&g_Z[((b*NPIX + i1.y) << 6) + c4]);
    acc = f4add(acc, *(const float4*)&g_Z[((b*NPIX + i1.z) << 6) + c4]);
    acc = f4add(acc, *(const float4*)&g_Z[((b*NPIX + i1.w) << 6) + c4]);
    acc = f4add(acc, *(const float4*)&g_Z[((b*NPIX + i2.x) << 6) + c4]);
    acc = f4add(acc, *(const float4*)&g_Z[((b*NPIX + i2.y) << 6) + c4]);
    *(float4*)&g_Y[((b*NPIX + e) << 6) + c4] = acc;
}

// ---------------- K8/K11: vertex gather: block per vertex, 16 slices float4
__global__ void k_vertex()
{
    int b = blockIdx.y, u = blockIdx.x, t = threadIdx.x;
    int c4 = (t & 15) * 4, s = t >> 4;
    __shared__ float4 red[256];
    int o0 = g_off[b*(NPIX+1) + u];
    int o1 = g_off[b*(NPIX+1) + u + 1];
    float4 acc = make_float4(0.f, 0.f, 0.f, 0.f);
    for (int p = o0 + s; p < o1; p += 16) {
        int e = g_ecol[b*NNZ + p];
        acc = f4add(acc, *(const float4*)&g_Y[((b*NPIX + e) << 6) + c4]);
    }
    red[t] = acc; __syncthreads();
    if (t < 128) red[t] = f4add(red[t], red[t+128]); __syncthreads();
    if (t < 64)  red[t] = f4add(red[t], red[t+64]);  __syncthreads();
    if (t < 32)  red[t] = f4add(red[t], red[t+32]);  __syncthreads();
    if (t < 16) {
        float4 tot = f4add(red[t], red[t+16]);
        float sc = g_dv2[b*NPIX + u];
        float4 o;
        o.x = fmaxf(tot.x * sc, 0.f);
        o.y = fmaxf(tot.y * sc, 0.f);
        o.z = fmaxf(tot.z * sc, 0.f);
        o.w = fmaxf(tot.w * sc, 0.f);
        *(float4*)&g_Hf[((b*NPIX + u) << 6) + t*4] = o;
    }
}

// ---------------- K12: final 1x1 conv + relu + per-batch sum
__global__ void k_final(const float* __restrict__ wc,
                        const float* __restrict__ bc,
                        float* __restrict__ out)
{
    int b = blockIdx.y, t = threadIdx.x;
    __shared__ float ws[NC];
    __shared__ float red[256];
    if (t < NC) ws[t] = wc[t];
    __syncthreads();
    const float* hb = g_Hf + (size_t)b * NPIX * NC;   // raw reshape: (C, NPIX)
    int p = blockIdx.x * 256 + t;
    float lsum = 0.f;
    if (p < NPIX) {
        float acc = bc[0];
        #pragma unroll
        for (int c = 0; c < NC; c++) acc += hb[c*NPIX + p] * ws[c];
        lsum = fmaxf(acc, 0.f);
    }
    red[t] = lsum; __syncthreads();
    for (int s = 128; s > 0; s >>= 1) { if (t < s) red[t] += red[t+s]; __syncthreads(); }
    if (t == 0) atomicAdd(&out[b], red[0]);
}

// ---------------- launch ----------------
extern "C" void kernel_launch(void* const* d_in, const int* in_sizes, int n_in,
                              void* d_out, int out_size)
{
    const float* x      = (const float*)d_in[0];
    const float* w_con1 = (const float*)d_in[1];
    const float* b_con1 = (const float*)d_in[2];
    const float* W1     = (const float*)d_in[3];
    const float* b1     = (const float*)d_in[4];
    const float* W2     = (const float*)d_in[5];
    const float* b2     = (const float*)d_in[6];
    const float* w_con2 = (const float*)d_in[7];
    const float* b_con2 = (const float*)d_in[8];
    float* out = (float*)d_out;

    k_convA<<<dim3(7, NB), 256>>>(x, w_con1, b_con1, out);
    k_sortA<<<NB, 1024>>>();
    k_walk<<<dim3(8, NB), 256>>>();
    k_scan<<<NB, 1024>>>();
    k_fill<<<dim3(63, NB), 256>>>();

    // layer 1
    k_gemm<<<dim3(NPIX / 64, NB), 256>>>(x, W1, b1, 0);
    k_edge<<<dim3(NPIX / 16, NB), 256>>>();
    k_vertex<<<dim3(NPIX, NB), 256>>>();

    // layer 2
    k_gemm<<<dim3(NPIX / 64, NB), 256>>>(nullptr, W2, b2, 1);
    k_edge<<<dim3(NPIX / 16, NB), 256>>>();
    k_vertex<<<dim3(NPIX, NB), 256>>>();

    k_final<<<dim3(7, NB), 256>>>(w_con2, b_con2, out);
}